// round 8
// baseline (speedup 1.0000x reference)
#include <cuda_runtime.h>
#include <cstdint>

#define NUSER 100000
#define NITEM 100000
#define NE    600000
#define NTOT  300000   // concatenated degree entries: [uu | iu | ui]

// ---------------- scratch (device globals; allocation-free) ----------------
__device__ float4 g_agg_uu[NUSER * 32];  // segsum of embed over uu edges
__device__ float4 g_agg_iu[NUSER * 32];
__device__ float4 g_agg_ui[NITEM * 32];
__device__ float4 g_Wh1_uu[NUSER * 4];   // [NU,16] layer-1 projections
__device__ float4 g_Wh1_iu[NITEM * 4];
__device__ float4 g_acc1_uu[NUSER * 4];
__device__ float4 g_acc1_iu[NUSER * 4];
__device__ int    g_deg[NTOT];
__device__ int    g_incl[NTOT];
__device__ int    g_rowstart[NTOT + 1];
__device__ int    g_cursor[NTOT];
__device__ int    g_bsum[512];
__device__ int    g_bsum_ex[512];
__device__ int    g_slot[3 * NE];

__device__ __forceinline__ float tf32r(float x) {
    uint32_t u;
    asm("cvt.rna.tf32.f32 %0, %1;" : "=r"(u) : "f"(x));
    return __uint_as_float(u);
}

// ---------------- CSR build ----------------
__global__ void zero_deg() {
    int i = blockIdx.x * blockDim.x + threadIdx.x;
    if (i < NTOT) g_deg[i] = 0;
}

__global__ void hist_all(const int* __restrict__ d0, const int* __restrict__ d1,
                         const int* __restrict__ d2) {
    int i = blockIdx.x * blockDim.x + threadIdx.x;
    if (i < NE) atomicAdd(&g_deg[d0[i]], 1);
    else if (i < 2 * NE) atomicAdd(&g_deg[100000 + d1[i - NE]], 1);
    else if (i < 3 * NE) atomicAdd(&g_deg[200000 + d2[i - 2 * NE]], 1);
}

__global__ void scan_k1() {
    __shared__ int s[1024];
    int tid = threadIdx.x;
    int i = blockIdx.x * 1024 + tid;
    int v = (i < NTOT) ? g_deg[i] : 0;
    s[tid] = v;
    __syncthreads();
    for (int o = 1; o < 1024; o <<= 1) {
        int t = 0;
        if (tid >= o) t = s[tid - o];
        __syncthreads();
        s[tid] += t;
        __syncthreads();
    }
    if (i < NTOT) g_incl[i] = s[tid];
    if (tid == 1023) g_bsum[blockIdx.x] = s[1023];
}

__global__ void scan_k2(int nblk) {
    __shared__ int s[512];
    int tid = threadIdx.x;
    int v = (tid < nblk) ? g_bsum[tid] : 0;
    s[tid] = v;
    __syncthreads();
    for (int o = 1; o < 512; o <<= 1) {
        int t = 0;
        if (tid >= o) t = s[tid - o];
        __syncthreads();
        s[tid] += t;
        __syncthreads();
    }
    g_bsum_ex[tid] = s[tid] - v;
}

__global__ void scan_k3() {
    int i = blockIdx.x * 1024 + threadIdx.x;
    if (i >= NTOT) return;
    int d = g_deg[i];
    int ex = g_incl[i] - d + g_bsum_ex[i >> 10];
    g_rowstart[i] = ex;
    g_cursor[i] = ex;
    if (i == NTOT - 1) g_rowstart[NTOT] = ex + d;
}

__global__ void fill_all(const int* __restrict__ s0, const int* __restrict__ d0,
                         const int* __restrict__ s1, const int* __restrict__ d1,
                         const int* __restrict__ s2, const int* __restrict__ d2) {
    int i = blockIdx.x * blockDim.x + threadIdx.x;
    int off, sv, dv;
    if (i < NE)            { off = 0;      sv = s0[i];          dv = d0[i]; }
    else if (i < 2 * NE)   { off = 100000; sv = s1[i - NE];     dv = d1[i - NE]; }
    else if (i < 3 * NE)   { off = 200000; sv = s2[i - 2 * NE]; dv = d2[i - 2 * NE]; }
    else return;
    int pos = atomicAdd(&g_cursor[off + dv], 1);
    g_slot[pos] = sv;
}

// ---------------- CSR gather-reduce of raw embeddings: warp per dst ----------
__global__ void reduce128(const float4* __restrict__ E, int which) {
    float4* agg = (which == 0) ? g_agg_uu : (which == 1) ? g_agg_iu : g_agg_ui;
    int w = (blockIdx.x * blockDim.x + threadIdx.x) >> 5;
    int lane = threadIdx.x & 31;
    if (w >= 100000) return;
    int off = which * 100000;
    int beg = g_rowstart[off + w];
    int end = g_rowstart[off + w + 1];
    float4 s = make_float4(0.f, 0.f, 0.f, 0.f);
    for (int j = beg; j < end; j++) {
        int sc = g_slot[j];
        float4 v = E[(size_t)sc * 32 + lane];
        s.x += v.x; s.y += v.y; s.z += v.z; s.w += v.w;
    }
    agg[(size_t)w * 32 + lane] = s;
}

// ---------------- fused layer-0 GEMM (+dual etype) + relu + layer-1 GEMM ----
// h = relu( (aggA/degA)@WA + bA*[degA>0]  [+ (aggB/degB)@WB + bB*[degB>0]] )
// out = h @ W1 + b1   -> Y1 [M,16]
// Device-global pointers selected INSIDE the kernel (never from host).
// 128x128 block tile, BK=16, 256 thr = 8 warps (4m x 2n), tf32 m16n8k8.
template <bool DUAL>
__global__ __launch_bounds__(256) void fused_layer(
    const float* __restrict__ WA, const float* __restrict__ bA,
    const float* __restrict__ WB, const float* __restrict__ bB,
    const float* __restrict__ W1, const float* __restrict__ b1) {
    // internal binding: DUAL -> user path, !DUAL -> item path
    const float4* aggA = DUAL ? g_agg_uu : g_agg_ui;
    const float4* aggB = DUAL ? g_agg_iu : g_agg_ui;   // unused when !DUAL
    float* Y1 = DUAL ? (float*)g_Wh1_uu : (float*)g_Wh1_iu;
    const int degOffA = DUAL ? 0 : 200000;
    const int degOffB = 100000;
    const int M = DUAL ? NUSER : NITEM;

    __shared__ __align__(16) float Am[128][20];
    __shared__ __align__(16) float Bsm[16][136];
    __shared__ __align__(16) float Ws1[128 * 20];
    __shared__ float part[128 * 33];
    __shared__ float bAs[128], bBs[128], b1s[16];

    const int tid = threadIdx.x;
    const int lane = tid & 31;
    const int wid = tid >> 5;
    const int warp_m = wid & 3;
    const int warp_n = wid >> 2;
    const int bm = blockIdx.x * 128;
    const int g = lane >> 2;
    const int t = lane & 3;

    const int fA0 = tid, fA1 = tid + 256;
    const int mA0 = fA0 >> 2, kqA0 = fA0 & 3;
    const int mA1 = fA1 >> 2, kqA1 = fA1 & 3;
    const int kB0 = fA0 >> 5, nB0 = (fA0 & 31) * 4;
    const int kB1 = fA1 >> 5, nB1 = (fA1 & 31) * 4;
    const int rowA0 = bm + mA0, rowA1 = bm + mA1;

    // stage W1 (stride 20), biases
#pragma unroll
    for (int i = 0; i < 8; i++) {
        int f = tid + i * 256;            // 0..2047
        int k = f >> 4, j = f & 15;
        Ws1[k * 20 + j] = W1[k * 16 + j];
    }
    if (tid < 128) { bAs[tid] = bA[tid]; bBs[tid] = DUAL ? bB[tid] : 0.f; }
    if (tid < 16) b1s[tid] = b1[tid];

    float c[2][8][4];
#pragma unroll
    for (int mt = 0; mt < 2; mt++)
#pragma unroll
        for (int nt = 0; nt < 8; nt++)
#pragma unroll
            for (int q = 0; q < 4; q++) c[mt][nt][q] = 0.f;

    const int NIT = DUAL ? 16 : 8;
    for (int it = 0; it < NIT; it++) {
        const bool pass2 = DUAL && (it >= 8);
        const float4* A = pass2 ? aggB : aggA;
        const float* Wm = pass2 ? WB : WA;
        const int doff = pass2 ? degOffB : degOffA;
        const int k0 = (it & 7) * 16;

        // stage A (row-scaled by 1/max(deg,1)) and B with tf32 rounding
        float4 ra0 = make_float4(0.f, 0.f, 0.f, 0.f);
        float4 ra1 = make_float4(0.f, 0.f, 0.f, 0.f);
        if (rowA0 < M) {
            float s = 1.f / fmaxf((float)g_deg[doff + rowA0], 1.f);
            float4 v = A[(size_t)rowA0 * 32 + (k0 >> 2) + kqA0];
            ra0 = make_float4(v.x * s, v.y * s, v.z * s, v.w * s);
        }
        if (rowA1 < M) {
            float s = 1.f / fmaxf((float)g_deg[doff + rowA1], 1.f);
            float4 v = A[(size_t)rowA1 * 32 + (k0 >> 2) + kqA1];
            ra1 = make_float4(v.x * s, v.y * s, v.z * s, v.w * s);
        }
        float4 rb0 = *(const float4*)(Wm + (size_t)(k0 + kB0) * 128 + nB0);
        float4 rb1 = *(const float4*)(Wm + (size_t)(k0 + kB1) * 128 + nB1);
        __syncthreads();   // protect previous iter's smem reads
        {
            float4 u;
            u.x = tf32r(ra0.x); u.y = tf32r(ra0.y); u.z = tf32r(ra0.z); u.w = tf32r(ra0.w);
            *(float4*)&Am[mA0][kqA0 * 4] = u;
            u.x = tf32r(ra1.x); u.y = tf32r(ra1.y); u.z = tf32r(ra1.z); u.w = tf32r(ra1.w);
            *(float4*)&Am[mA1][kqA1 * 4] = u;
            u.x = tf32r(rb0.x); u.y = tf32r(rb0.y); u.z = tf32r(rb0.z); u.w = tf32r(rb0.w);
            *(float4*)&Bsm[kB0][nB0] = u;
            u.x = tf32r(rb1.x); u.y = tf32r(rb1.y); u.z = tf32r(rb1.z); u.w = tf32r(rb1.w);
            *(float4*)&Bsm[kB1][nB1] = u;
        }
        __syncthreads();

#pragma unroll
        for (int kk = 0; kk < 16; kk += 8) {
            uint32_t a[2][4], b[8][2];
#pragma unroll
            for (int mt = 0; mt < 2; mt++) {
                int r = warp_m * 32 + mt * 16 + g;
                a[mt][0] = __float_as_uint(Am[r][kk + t]);
                a[mt][1] = __float_as_uint(Am[r + 8][kk + t]);
                a[mt][2] = __float_as_uint(Am[r][kk + t + 4]);
                a[mt][3] = __float_as_uint(Am[r + 8][kk + t + 4]);
            }
#pragma unroll
            for (int nt = 0; nt < 8; nt++) {
                int cn = warp_n * 64 + nt * 8 + g;
                b[nt][0] = __float_as_uint(Bsm[kk + t][cn]);
                b[nt][1] = __float_as_uint(Bsm[kk + t + 4][cn]);
            }
#pragma unroll
            for (int mt = 0; mt < 2; mt++)
#pragma unroll
                for (int nt = 0; nt < 8; nt++) {
                    asm volatile(
                        "mma.sync.aligned.m16n8k8.row.col.f32.tf32.tf32.f32 "
                        "{%0,%1,%2,%3},{%4,%5,%6,%7},{%8,%9},{%0,%1,%2,%3};"
                        : "+f"(c[mt][nt][0]), "+f"(c[mt][nt][1]),
                          "+f"(c[mt][nt][2]), "+f"(c[mt][nt][3])
                        : "r"(a[mt][0]), "r"(a[mt][1]), "r"(a[mt][2]), "r"(a[mt][3]),
                          "r"(b[nt][0]), "r"(b[nt][1]));
                }
        }
    }

    // epilogue: bias*indicator + relu (in registers)
#pragma unroll
    for (int mt = 0; mt < 2; mt++) {
#pragma unroll
        for (int half = 0; half < 2; half++) {
            int row = bm + warp_m * 32 + mt * 16 + half * 8 + g;
            float indA = 0.f, indB = 0.f;
            if (row < M) {
                indA = (g_deg[degOffA + row] > 0) ? 1.f : 0.f;
                if (DUAL) indB = (g_deg[degOffB + row] > 0) ? 1.f : 0.f;
            }
#pragma unroll
            for (int nt = 0; nt < 8; nt++) {
                int col = warp_n * 64 + nt * 8 + t * 2;
#pragma unroll
                for (int q = 0; q < 2; q++) {
                    float v = c[mt][nt][half * 2 + q]
                            + bAs[col + q] * indA + bBs[col + q] * indB;
                    c[mt][nt][half * 2 + q] = fmaxf(v, 0.f);
                }
            }
        }
    }

    __syncthreads();  // mainloop smem dead; Ws1 ready

    // layer-1 partial products: per thread 16 cols of h -> 16 outputs, 4 rows
#pragma unroll
    for (int mt = 0; mt < 2; mt++) {
#pragma unroll
        for (int half = 0; half < 2; half++) {
            float pr[16];
#pragma unroll
            for (int j = 0; j < 16; j++) pr[j] = 0.f;
#pragma unroll
            for (int nt = 0; nt < 8; nt++) {
                int col = warp_n * 64 + nt * 8 + t * 2;
                float h0 = c[mt][nt][half * 2 + 0];
                float h1 = c[mt][nt][half * 2 + 1];
                const float* w0 = &Ws1[col * 20];
                const float* w1 = &Ws1[(col + 1) * 20];
#pragma unroll
                for (int j = 0; j < 16; j++)
                    pr[j] = fmaf(h0, w0[j], fmaf(h1, w1[j], pr[j]));
            }
#pragma unroll
            for (int j = 0; j < 16; j++) {
                pr[j] += __shfl_xor_sync(0xffffffff, pr[j], 1);
                pr[j] += __shfl_xor_sync(0xffffffff, pr[j], 2);
            }
            if (t == 0) {
                int rl = warp_m * 32 + mt * 16 + half * 8 + g;
#pragma unroll
                for (int j = 0; j < 16; j++)
                    part[rl * 33 + warp_n * 16 + j] = pr[j];
            }
        }
    }
    __syncthreads();

    // combine warp_n halves + b1, write Y1
    {
        int rl = tid >> 1;
        int jb = (tid & 1) * 8;
        int row = bm + rl;
        if (row < M) {
#pragma unroll
            for (int j = 0; j < 8; j++) {
                float o = part[rl * 33 + jb + j] + part[rl * 33 + 16 + jb + j] + b1s[jb + j];
                Y1[(size_t)row * 16 + jb + j] = o;
            }
        }
    }
}

// ---------------- CSR gather-reduce, 16-wide: 4 lanes per dst node ----------
__global__ void reduce16(int which) {
    const float4* Wh = (which == 0) ? g_Wh1_uu : g_Wh1_iu;
    float4* acc = (which == 0) ? g_acc1_uu : g_acc1_iu;
    int id = blockIdx.x * blockDim.x + threadIdx.x;
    int n = id >> 2, part = id & 3;
    if (n >= 100000) return;
    int off = which * 100000;                 // etype 0 = uu, 1 = iu
    int beg = g_rowstart[off + n];
    int end = g_rowstart[off + n + 1];
    float4 s = make_float4(0.f, 0.f, 0.f, 0.f);
    for (int j = beg; j < end; j++) {
        int sc = g_slot[j];
        float4 v = Wh[(size_t)sc * 4 + part];
        s.x += v.x; s.y += v.y; s.z += v.z; s.w += v.w;
    }
    acc[(size_t)n * 4 + part] = s;
}

// ---------------- final combine: mean + mean (no relu) ----------------
__global__ void final_out(float4* __restrict__ out) {
    int i = blockIdx.x * blockDim.x + threadIdx.x;
    if (i >= NUSER * 4) return;
    int node = i >> 2;
    float iu = 1.f / fmaxf((float)g_deg[node], 1.f);
    float ii = 1.f / fmaxf((float)g_deg[100000 + node], 1.f);
    float4 a = g_acc1_uu[i], c = g_acc1_iu[i];
    float4 o;
    o.x = a.x * iu + c.x * ii;
    o.y = a.y * iu + c.y * ii;
    o.z = a.z * iu + c.z * ii;
    o.w = a.w * iu + c.w * ii;
    out[i] = o;
}

// ---------------- launch ----------------
extern "C" void kernel_launch(void* const* d_in, const int* in_sizes, int n_in,
                              void* d_out, int out_size) {
    const float4* embed_user = (const float4*)d_in[0];
    const float4* embed_item = (const float4*)d_in[1];
    const int* src_uu = (const int*)d_in[2];
    const int* dst_uu = (const int*)d_in[3];
    const int* src_ui = (const int*)d_in[4];
    const int* dst_ui = (const int*)d_in[5];
    const int* src_iu = (const int*)d_in[6];
    const int* dst_iu = (const int*)d_in[7];
    const float* W0_uu = (const float*)d_in[8];
    const float* b0_uu = (const float*)d_in[9];
    const float* W0_ui = (const float*)d_in[10];
    const float* b0_ui = (const float*)d_in[11];
    const float* W0_iu = (const float*)d_in[12];
    const float* b0_iu = (const float*)d_in[13];
    const float* W1_uu = (const float*)d_in[14];
    const float* b1_uu = (const float*)d_in[15];
    const float* W1_iu = (const float*)d_in[18];
    const float* b1_iu = (const float*)d_in[19];

    const int nscan = (NTOT + 1023) / 1024;  // 293
    const int e3blk = (3 * NE + 255) / 256;

    // ---- CSR build (shared by both layers) ----
    zero_deg<<<(NTOT + 255) / 256, 256>>>();
    hist_all<<<e3blk, 256>>>(dst_uu, dst_iu, dst_ui);
    scan_k1<<<nscan, 1024>>>();
    scan_k2<<<1, 512>>>(nscan);
    scan_k3<<<nscan, 1024>>>();
    fill_all<<<e3blk, 256>>>(src_uu, dst_uu, src_iu, dst_iu, src_ui, dst_ui);

    // ---- aggregate raw embeddings (uu, ui share embed_user -> L2 reuse) ----
    int rblk = (100000 * 32 + 255) / 256;
    reduce128<<<rblk, 256>>>(embed_user, 0);   // uu
    reduce128<<<rblk, 256>>>(embed_user, 2);   // ui
    reduce128<<<rblk, 256>>>(embed_item, 1);   // iu

    // ---- fused layer-0 (+relu) + layer-1 projection ----
    fused_layer<true><<<(NUSER + 127) / 128, 256>>>(
        W0_uu, b0_uu, W0_iu, b0_iu, W1_uu, b1_uu);
    fused_layer<false><<<(NITEM + 127) / 128, 256>>>(
        W0_ui, b0_ui, W0_ui, b0_ui, W1_iu, b1_iu);

    // ---- layer-1 aggregation + output ----
    reduce16<<<(100000 * 4 + 255) / 256, 256>>>(0);
    reduce16<<<(100000 * 4 + 255) / 256, 256>>>(1);
    final_out<<<(NUSER * 4 + 255) / 256, 256>>>((float4*)d_out);
}

// round 10
// speedup vs baseline: 1.0651x; 1.0651x over previous
#include <cuda_runtime.h>
#include <cstdint>

#define NUSER 100000
#define NITEM 100000
#define NE    600000
#define NTOT  300000   // concatenated degree entries: [uu | iu | ui]

// ---------------- scratch (device globals; allocation-free) ----------------
__device__ float4 g_agg_uu[NUSER * 32];  // segsum of embed over uu edges
__device__ float4 g_agg_iu[NUSER * 32];
__device__ float4 g_agg_ui[NITEM * 32];
__device__ float4 g_Wh1_uu[NUSER * 4];   // [NU,16] layer-1 projections
__device__ float4 g_Wh1_iu[NITEM * 4];
__device__ int    g_deg[NTOT];
__device__ int    g_incl[NTOT];
__device__ int    g_rowstart[NTOT + 1];
__device__ int    g_cursor[NTOT];
__device__ int    g_bsum[512];
__device__ int    g_bsum_ex[512];
__device__ int    g_slot[3 * NE];
__device__ float  g_sink;

__device__ __forceinline__ float tf32r(float x) {
    uint32_t u;
    asm("cvt.rna.tf32.f32 %0, %1;" : "=r"(u) : "f"(x));
    return __uint_as_float(u);
}

// ---------------- CSR build ----------------
__global__ void zero_deg() {
    int i = blockIdx.x * blockDim.x + threadIdx.x;
    if (i < NTOT) g_deg[i] = 0;
}

__global__ void hist_all(const int* __restrict__ d0, const int* __restrict__ d1,
                         const int* __restrict__ d2) {
    int i = blockIdx.x * blockDim.x + threadIdx.x;
    if (i < NE) atomicAdd(&g_deg[d0[i]], 1);
    else if (i < 2 * NE) atomicAdd(&g_deg[100000 + d1[i - NE]], 1);
    else if (i < 3 * NE) atomicAdd(&g_deg[200000 + d2[i - 2 * NE]], 1);
}

__global__ void scan_k1() {
    __shared__ int s[1024];
    int tid = threadIdx.x;
    int i = blockIdx.x * 1024 + tid;
    int v = (i < NTOT) ? g_deg[i] : 0;
    s[tid] = v;
    __syncthreads();
    for (int o = 1; o < 1024; o <<= 1) {
        int t = 0;
        if (tid >= o) t = s[tid - o];
        __syncthreads();
        s[tid] += t;
        __syncthreads();
    }
    if (i < NTOT) g_incl[i] = s[tid];
    if (tid == 1023) g_bsum[blockIdx.x] = s[1023];
}

__global__ void scan_k2(int nblk) {
    __shared__ int s[512];
    int tid = threadIdx.x;
    int v = (tid < nblk) ? g_bsum[tid] : 0;
    s[tid] = v;
    __syncthreads();
    for (int o = 1; o < 512; o <<= 1) {
        int t = 0;
        if (tid >= o) t = s[tid - o];
        __syncthreads();
        s[tid] += t;
        __syncthreads();
    }
    g_bsum_ex[tid] = s[tid] - v;
}

__global__ void scan_k3() {
    int i = blockIdx.x * 1024 + threadIdx.x;
    if (i >= NTOT) return;
    int d = g_deg[i];
    int ex = g_incl[i] - d + g_bsum_ex[i >> 10];
    g_rowstart[i] = ex;
    g_cursor[i] = ex;
    if (i == NTOT - 1) g_rowstart[NTOT] = ex + d;
}

__global__ void fill_all(const int* __restrict__ s0, const int* __restrict__ d0,
                         const int* __restrict__ s1, const int* __restrict__ d1,
                         const int* __restrict__ s2, const int* __restrict__ d2) {
    int i = blockIdx.x * blockDim.x + threadIdx.x;
    int off, sv, dv;
    if (i < NE)            { off = 0;      sv = s0[i];          dv = d0[i]; }
    else if (i < 2 * NE)   { off = 100000; sv = s1[i - NE];     dv = d1[i - NE]; }
    else if (i < 3 * NE)   { off = 200000; sv = s2[i - 2 * NE]; dv = d2[i - 2 * NE]; }
    else return;
    int pos = atomicAdd(&g_cursor[off + dv], 1);
    g_slot[pos] = sv;
}

// ---------------- streaming prewarm: pull a table into L2 ----------------
__global__ void prewarm(const float4* __restrict__ p, int n4) {
    int i = blockIdx.x * blockDim.x + threadIdx.x;
    int stride = gridDim.x * blockDim.x;
    float s = 0.f;
    for (int j = i; j < n4; j += stride) {
        float4 v = __ldg(&p[j]);
        s += v.x + v.y + v.z + v.w;
    }
    if (s == 1.2345678e30f) g_sink = s;   // never true; defeats DCE
}

// ---------------- CSR gather-reduces (warp per dst node, L2-hot table) ------
// uu + ui share embed_user: one launch, 200k warps.
__global__ void reduce128_user(const float4* __restrict__ E) {
    int w = (blockIdx.x * blockDim.x + threadIdx.x) >> 5;
    int lane = threadIdx.x & 31;
    if (w >= 200000) return;
    bool is_ui = (w >= 100000);
    int node = is_ui ? w - 100000 : w;
    int off  = is_ui ? 200000 : 0;
    float4* agg = is_ui ? g_agg_ui : g_agg_uu;
    int beg = g_rowstart[off + node];
    int end = g_rowstart[off + node + 1];
    float4 s = make_float4(0.f, 0.f, 0.f, 0.f);
    for (int j = beg; j < end; j++) {
        int sc = g_slot[j];
        float4 v = __ldg(&E[(size_t)sc * 32 + lane]);
        s.x += v.x; s.y += v.y; s.z += v.z; s.w += v.w;
    }
    __stcs(&agg[(size_t)node * 32 + lane], s);   // evict-first: keep E resident
}

__global__ void reduce128_item(const float4* __restrict__ E) {
    int w = (blockIdx.x * blockDim.x + threadIdx.x) >> 5;
    int lane = threadIdx.x & 31;
    if (w >= 100000) return;
    int beg = g_rowstart[100000 + w];
    int end = g_rowstart[100000 + w + 1];
    float4 s = make_float4(0.f, 0.f, 0.f, 0.f);
    for (int j = beg; j < end; j++) {
        int sc = g_slot[j];
        float4 v = __ldg(&E[(size_t)sc * 32 + lane]);
        s.x += v.x; s.y += v.y; s.z += v.z; s.w += v.w;
    }
    __stcs(&g_agg_iu[(size_t)w * 32 + lane], s);
}

// ---------------- fused layer-0 GEMM (+dual etype) + relu + layer-1 GEMM ----
// h = relu( (aggA/degA)@WA + bA*[degA>0]  [+ (aggB/degB)@WB + bB*[degB>0]] )
// Y1 = h @ W1 + b1.  128x128 tile, BK=16, tf32 m16n8k8, DOUBLE-BUFFERED smem.
// Mainloop buffers and epilogue (Ws1, part) overlay via a phase union.
template <bool DUAL>
__global__ __launch_bounds__(256) void fused_layer(
    const float* __restrict__ WA, const float* __restrict__ bA,
    const float* __restrict__ WB, const float* __restrict__ bB,
    const float* __restrict__ W1, const float* __restrict__ b1) {
    const float4* aggA = DUAL ? g_agg_uu : g_agg_ui;
    const float4* aggB = g_agg_iu;
    float* Y1 = DUAL ? (float*)g_Wh1_uu : (float*)g_Wh1_iu;
    const int degOffA = DUAL ? 0 : 200000;
    const int degOffB = 100000;
    const int M = DUAL ? NUSER : NITEM;

    // phase union: mainloop 37888B | epilogue 27136B
    __shared__ __align__(16) char smem_raw[37888];
    float (*Am)[20]   = (float(*)[20])smem_raw;              // [256][20]: 2 bufs x 128 rows
    float (*Bsm)[136] = (float(*)[136])(smem_raw + 20480);   // [32][136]: 2 bufs x 16 rows
    float* Ws1  = (float*)smem_raw;                          // [128*20] epilogue
    float* part = (float*)(smem_raw + 10240);                // [128*33] epilogue
    __shared__ float bAs[128], bBs[128], b1s[16];

    const int tid = threadIdx.x;
    const int lane = tid & 31;
    const int wid = tid >> 5;
    const int warp_m = wid & 3;
    const int warp_n = wid >> 2;
    const int bm = blockIdx.x * 128;
    const int g = lane >> 2;
    const int t = lane & 3;

    const int fA0 = tid, fA1 = tid + 256;
    const int mA0 = fA0 >> 2, kqA0 = fA0 & 3;
    const int mA1 = fA1 >> 2, kqA1 = fA1 & 3;
    const int kB0 = fA0 >> 5, nB0 = (fA0 & 31) * 4;
    const int kB1 = fA1 >> 5, nB1 = (fA1 & 31) * 4;
    const int rowA0 = bm + mA0, rowA1 = bm + mA1;

    if (tid < 128) { bAs[tid] = bA[tid]; bBs[tid] = DUAL ? bB[tid] : 0.f; }
    if (tid < 16) b1s[tid] = b1[tid];

    float c[2][8][4];
#pragma unroll
    for (int mt = 0; mt < 2; mt++)
#pragma unroll
        for (int nt = 0; nt < 8; nt++)
#pragma unroll
            for (int q = 0; q < 4; q++) c[mt][nt][q] = 0.f;

    float4 ra0, ra1, rb0, rb1;

#define LOAD_REGS(IT)                                                             \
    {                                                                             \
        const bool pass2 = DUAL && ((IT) >= 8);                                   \
        const float4* A = pass2 ? aggB : aggA;                                    \
        const float* Wm = pass2 ? WB : WA;                                        \
        const int doff = pass2 ? degOffB : degOffA;                               \
        const int k0 = ((IT) & 7) * 16;                                           \
        ra0 = make_float4(0.f, 0.f, 0.f, 0.f);                                    \
        ra1 = make_float4(0.f, 0.f, 0.f, 0.f);                                    \
        if (rowA0 < M) {                                                          \
            float s = 1.f / fmaxf((float)g_deg[doff + rowA0], 1.f);               \
            float4 v = A[(size_t)rowA0 * 32 + (k0 >> 2) + kqA0];                  \
            ra0 = make_float4(v.x * s, v.y * s, v.z * s, v.w * s);                \
        }                                                                         \
        if (rowA1 < M) {                                                          \
            float s = 1.f / fmaxf((float)g_deg[doff + rowA1], 1.f);               \
            float4 v = A[(size_t)rowA1 * 32 + (k0 >> 2) + kqA1];                  \
            ra1 = make_float4(v.x * s, v.y * s, v.z * s, v.w * s);                \
        }                                                                         \
        rb0 = *(const float4*)(Wm + (size_t)(k0 + kB0) * 128 + nB0);              \
        rb1 = *(const float4*)(Wm + (size_t)(k0 + kB1) * 128 + nB1);              \
    }

#define STORE_BUF(B)                                                              \
    {                                                                             \
        float4 u;                                                                 \
        u.x = tf32r(ra0.x); u.y = tf32r(ra0.y); u.z = tf32r(ra0.z); u.w = tf32r(ra0.w); \
        *(float4*)&Am[(B) * 128 + mA0][kqA0 * 4] = u;                             \
        u.x = tf32r(ra1.x); u.y = tf32r(ra1.y); u.z = tf32r(ra1.z); u.w = tf32r(ra1.w); \
        *(float4*)&Am[(B) * 128 + mA1][kqA1 * 4] = u;                             \
        u.x = tf32r(rb0.x); u.y = tf32r(rb0.y); u.z = tf32r(rb0.z); u.w = tf32r(rb0.w); \
        *(float4*)&Bsm[(B) * 16 + kB0][nB0] = u;                                  \
        u.x = tf32r(rb1.x); u.y = tf32r(rb1.y); u.z = tf32r(rb1.z); u.w = tf32r(rb1.w); \
        *(float4*)&Bsm[(B) * 16 + kB1][nB1] = u;                                  \
    }

    const int NIT = DUAL ? 16 : 8;
    LOAD_REGS(0);
    STORE_BUF(0);
    __syncthreads();

    int cur = 0;
    for (int it = 0; it < NIT; it++) {
        if (it + 1 < NIT) LOAD_REGS(it + 1);
        // compute from buffer cur
#pragma unroll
        for (int kk = 0; kk < 16; kk += 8) {
            uint32_t a[2][4], b[8][2];
#pragma unroll
            for (int mt = 0; mt < 2; mt++) {
                int r = cur * 128 + warp_m * 32 + mt * 16 + g;
                a[mt][0] = __float_as_uint(Am[r][kk + t]);
                a[mt][1] = __float_as_uint(Am[r + 8][kk + t]);
                a[mt][2] = __float_as_uint(Am[r][kk + t + 4]);
                a[mt][3] = __float_as_uint(Am[r + 8][kk + t + 4]);
            }
#pragma unroll
            for (int nt = 0; nt < 8; nt++) {
                int cn = warp_n * 64 + nt * 8 + g;
                b[nt][0] = __float_as_uint(Bsm[cur * 16 + kk + t][cn]);
                b[nt][1] = __float_as_uint(Bsm[cur * 16 + kk + t + 4][cn]);
            }
#pragma unroll
            for (int mt = 0; mt < 2; mt++)
#pragma unroll
                for (int nt = 0; nt < 8; nt++) {
                    asm volatile(
                        "mma.sync.aligned.m16n8k8.row.col.f32.tf32.tf32.f32 "
                        "{%0,%1,%2,%3},{%4,%5,%6,%7},{%8,%9},{%0,%1,%2,%3};"
                        : "+f"(c[mt][nt][0]), "+f"(c[mt][nt][1]),
                          "+f"(c[mt][nt][2]), "+f"(c[mt][nt][3])
                        : "r"(a[mt][0]), "r"(a[mt][1]), "r"(a[mt][2]), "r"(a[mt][3]),
                          "r"(b[nt][0]), "r"(b[nt][1]));
                }
        }
        if (it + 1 < NIT) {
            STORE_BUF(cur ^ 1);
            __syncthreads();
            cur ^= 1;
        }
    }
#undef LOAD_REGS
#undef STORE_BUF

    // ---- epilogue phase: mainloop smem dead after this sync ----
    __syncthreads();

    // stage W1 into the union (stride 20)
#pragma unroll
    for (int i = 0; i < 8; i++) {
        int f = tid + i * 256;            // 0..2047
        Ws1[(f >> 4) * 20 + (f & 15)] = W1[f];
    }

    // bias*indicator + relu (registers only; overlaps Ws1 staging)
#pragma unroll
    for (int mt = 0; mt < 2; mt++) {
#pragma unroll
        for (int half = 0; half < 2; half++) {
            int row = bm + warp_m * 32 + mt * 16 + half * 8 + g;
            float indA = 0.f, indB = 0.f;
            if (row < M) {
                indA = (g_deg[degOffA + row] > 0) ? 1.f : 0.f;
                if (DUAL) indB = (g_deg[degOffB + row] > 0) ? 1.f : 0.f;
            }
#pragma unroll
            for (int nt = 0; nt < 8; nt++) {
                int col = warp_n * 64 + nt * 8 + t * 2;
#pragma unroll
                for (int q = 0; q < 2; q++) {
                    float v = c[mt][nt][half * 2 + q]
                            + bAs[col + q] * indA + bBs[col + q] * indB;
                    c[mt][nt][half * 2 + q] = fmaxf(v, 0.f);
                }
            }
        }
    }
    __syncthreads();   // Ws1 visible

    // layer-1 partial products: per thread 16 cols of h -> 16 outputs, 4 rows
#pragma unroll
    for (int mt = 0; mt < 2; mt++) {
#pragma unroll
        for (int half = 0; half < 2; half++) {
            float pr[16];
#pragma unroll
            for (int j = 0; j < 16; j++) pr[j] = 0.f;
#pragma unroll
            for (int nt = 0; nt < 8; nt++) {
                int col = warp_n * 64 + nt * 8 + t * 2;
                float h0 = c[mt][nt][half * 2 + 0];
                float h1 = c[mt][nt][half * 2 + 1];
                const float* w0 = &Ws1[col * 20];
                const float* w1 = &Ws1[(col + 1) * 20];
#pragma unroll
                for (int j = 0; j < 16; j++)
                    pr[j] = fmaf(h0, w0[j], fmaf(h1, w1[j], pr[j]));
            }
#pragma unroll
            for (int j = 0; j < 16; j++) {
                pr[j] += __shfl_xor_sync(0xffffffff, pr[j], 1);
                pr[j] += __shfl_xor_sync(0xffffffff, pr[j], 2);
            }
            if (t == 0) {
                int rl = warp_m * 32 + mt * 16 + half * 8 + g;
#pragma unroll
                for (int j = 0; j < 16; j++)
                    part[rl * 33 + warp_n * 16 + j] = pr[j];
            }
        }
    }
    __syncthreads();

    // combine warp_n halves + b1, write Y1
    {
        int rl = tid >> 1;
        int jb = (tid & 1) * 8;
        int row = bm + rl;
        if (row < M) {
#pragma unroll
            for (int j = 0; j < 8; j++) {
                float o = part[rl * 33 + jb + j] + part[rl * 33 + 16 + jb + j] + b1s[jb + j];
                Y1[(size_t)row * 16 + jb + j] = o;
            }
        }
    }
}

// ---------------- layer-1 reduce (both etypes) + mean combine -> d_out ------
__global__ void reduce16_final(float4* __restrict__ out) {
    int id = blockIdx.x * blockDim.x + threadIdx.x;
    int n = id >> 2, part = id & 3;
    if (n >= NUSER) return;
    float4 s0 = make_float4(0.f, 0.f, 0.f, 0.f);
    {
        int beg = g_rowstart[n], end = g_rowstart[n + 1];
        for (int j = beg; j < end; j++) {
            int sc = g_slot[j];
            float4 v = __ldg(&g_Wh1_uu[(size_t)sc * 4 + part]);
            s0.x += v.x; s0.y += v.y; s0.z += v.z; s0.w += v.w;
        }
    }
    float4 s1 = make_float4(0.f, 0.f, 0.f, 0.f);
    {
        int beg = g_rowstart[100000 + n], end = g_rowstart[100000 + n + 1];
        for (int j = beg; j < end; j++) {
            int sc = g_slot[j];
            float4 v = __ldg(&g_Wh1_iu[(size_t)sc * 4 + part]);
            s1.x += v.x; s1.y += v.y; s1.z += v.z; s1.w += v.w;
        }
    }
    float iu = 1.f / fmaxf((float)g_deg[n], 1.f);
    float ii = 1.f / fmaxf((float)g_deg[100000 + n], 1.f);
    float4 o;
    o.x = s0.x * iu + s1.x * ii;
    o.y = s0.y * iu + s1.y * ii;
    o.z = s0.z * iu + s1.z * ii;
    o.w = s0.w * iu + s1.w * ii;
    out[(size_t)n * 4 + part] = o;
}

// ---------------- launch ----------------
extern "C" void kernel_launch(void* const* d_in, const int* in_sizes, int n_in,
                              void* d_out, int out_size) {
    const float4* embed_user = (const float4*)d_in[0];
    const float4* embed_item = (const float4*)d_in[1];
    const int* src_uu = (const int*)d_in[2];
    const int* dst_uu = (const int*)d_in[3];
    const int* src_ui = (const int*)d_in[4];
    const int* dst_ui = (const int*)d_in[5];
    const int* src_iu = (const int*)d_in[6];
    const int* dst_iu = (const int*)d_in[7];
    const float* W0_uu = (const float*)d_in[8];
    const float* b0_uu = (const float*)d_in[9];
    const float* W0_ui = (const float*)d_in[10];
    const float* b0_ui = (const float*)d_in[11];
    const float* W0_iu = (const float*)d_in[12];
    const float* b0_iu = (const float*)d_in[13];
    const float* W1_uu = (const float*)d_in[14];
    const float* b1_uu = (const float*)d_in[15];
    const float* W1_iu = (const float*)d_in[18];
    const float* b1_iu = (const float*)d_in[19];

    const int nscan = (NTOT + 1023) / 1024;  // 293
    const int e3blk = (3 * NE + 255) / 256;

    // ---- CSR build (shared by both layers) ----
    zero_deg<<<(NTOT + 255) / 256, 256>>>();
    hist_all<<<e3blk, 256>>>(dst_uu, dst_iu, dst_ui);
    scan_k1<<<nscan, 1024>>>();
    scan_k2<<<1, 512>>>(nscan);
    scan_k3<<<nscan, 1024>>>();
    fill_all<<<e3blk, 256>>>(src_uu, dst_uu, src_iu, dst_iu, src_ui, dst_ui);

    // ---- layer-0 aggregation of raw embeddings (prewarmed -> L2-hot gathers)
    prewarm<<<1184, 256>>>(embed_user, NUSER * 32);
    reduce128_user<<<(200000 * 32 + 255) / 256, 256>>>(embed_user);
    prewarm<<<1184, 256>>>(embed_item, NITEM * 32);
    reduce128_item<<<(100000 * 32 + 255) / 256, 256>>>(embed_item);

    // ---- fused layer-0 (+relu) + layer-1 projection ----
    fused_layer<true><<<(NUSER + 127) / 128, 256>>>(
        W0_uu, b0_uu, W0_iu, b0_iu, W1_uu, b1_uu);
    fused_layer<false><<<(NITEM + 127) / 128, 256>>>(
        W0_ui, b0_ui, W0_ui, b0_ui, W1_iu, b1_iu);

    // ---- layer-1 aggregation + mean combine -> output ----
    reduce16_final<<<(NUSER * 4 + 255) / 256, 256>>>((float4*)d_out);
}